// round 1
// baseline (speedup 1.0000x reference)
#include <cuda_runtime.h>

// Problem constants (fixed by the dataset)
constexpr int N  = 50000;
constexpr int E  = 800000;
constexpr int R  = 3;
constexpr int FIN  = 128;
constexpr int FHID = 128;
constexpr int FOUT = 64;

// Scratch (device globals; no allocation allowed)
__device__ int   g_dego[R * N];
__device__ int   g_degi[R * N];
__device__ float g_rso[R * N];
__device__ float g_rsi[R * N];
__device__ float g_xw1[(size_t)R * N * FHID];   // 76.8 MB
__device__ float g_acc[(size_t)N * FHID];       // 25.6 MB (layer1 accumulator / layer2 input)
__device__ float g_xw2[(size_t)R * N * FOUT];   // 38.4 MB

// ---------------- degrees ----------------
__global__ void k_deg_init() {
    int i = blockIdx.x * blockDim.x + threadIdx.x;
    if (i < R * N) { g_dego[i] = 1; g_degi[i] = 1; }  // self-loop
}

__global__ void k_deg_count(const int* __restrict__ src, const int* __restrict__ dst) {
    int i = blockIdx.x * blockDim.x + threadIdx.x;
    if (i < R * E) {
        int r = i / E;
        atomicAdd(&g_dego[r * N + src[i]], 1);
        atomicAdd(&g_degi[r * N + dst[i]], 1);
    }
}

__global__ void k_rsqrt() {
    int i = blockIdx.x * blockDim.x + threadIdx.x;
    if (i < R * N) {
        g_rso[i] = rsqrtf((float)g_dego[i]);
        g_rsi[i] = rsqrtf((float)g_degi[i]);
    }
}

// ---------------- GEMM: C_r = (relu?)(A) @ W_r  for r in grid.y ----------------
// A: [nrows, 128] row-major.  Wb: [R, 128, F] row-major.  Cb: [R, nrows, F].
template<int F, int TM, bool RELU>
__global__ __launch_bounds__(256)
void gemm_rel(const float* __restrict__ A, const float* __restrict__ Wb,
              float* __restrict__ Cb, int nrows) {
    constexpr int K  = 128;
    constexpr int KT = 16;
    constexpr int TN = 4;
    constexpr int NTC = F / TN;        // threads along cols (32 or 16)
    constexpr int NTR = 256 / NTC;     // threads along rows (8 or 16)
    constexpr int BM  = NTR * TM;      // 64
    static_assert(BM == 64, "block row tile must be 64");

    const int r = blockIdx.y;
    const float* B = Wb + (size_t)r * K * F;
    float* C = Cb + (size_t)r * nrows * F;
    const int row0 = blockIdx.x * BM;
    const int tid = threadIdx.x;
    const int tc = tid % NTC;
    const int tr = tid / NTC;

    __shared__ float sA[KT][BM + 4];
    __shared__ float sB[KT][F];

    float acc[TM][TN];
#pragma unroll
    for (int i = 0; i < TM; i++)
#pragma unroll
        for (int j = 0; j < TN; j++) acc[i][j] = 0.f;

    for (int k0 = 0; k0 < K; k0 += KT) {
        // A tile: 64 rows x 16 k, one float4 per thread, stored transposed
        {
            int m  = tid >> 2;
            int kq = tid & 3;
            int grow = row0 + m;
            float4 v = make_float4(0.f, 0.f, 0.f, 0.f);
            if (grow < nrows)
                v = *(const float4*)(A + (size_t)grow * K + k0 + kq * 4);
            if (RELU) {
                v.x = fmaxf(v.x, 0.f); v.y = fmaxf(v.y, 0.f);
                v.z = fmaxf(v.z, 0.f); v.w = fmaxf(v.w, 0.f);
            }
            sA[kq * 4 + 0][m] = v.x; sA[kq * 4 + 1][m] = v.y;
            sA[kq * 4 + 2][m] = v.z; sA[kq * 4 + 3][m] = v.w;
        }
        // B tile: 16 x F
        {
            constexpr int NF4 = KT * F / 4;
#pragma unroll
            for (int t = tid; t < NF4; t += 256) {
                int k  = t / (F / 4);
                int j4 = t % (F / 4);
                *(float4*)&sB[k][j4 * 4] = *(const float4*)(B + (size_t)(k0 + k) * F + j4 * 4);
            }
        }
        __syncthreads();
#pragma unroll
        for (int k = 0; k < KT; k++) {
            float a[TM], b[TN];
#pragma unroll
            for (int i = 0; i < TM; i += 4)
                *(float4*)&a[i] = *(const float4*)&sA[k][tr * TM + i];
            *(float4*)&b[0] = *(const float4*)&sB[k][tc * TN];
#pragma unroll
            for (int i = 0; i < TM; i++)
#pragma unroll
                for (int j = 0; j < TN; j++)
                    acc[i][j] = fmaf(a[i], b[j], acc[i][j]);
        }
        __syncthreads();
    }
#pragma unroll
    for (int i = 0; i < TM; i++) {
        int grow = row0 + tr * TM + i;
        if (grow < nrows)
            *(float4*)(C + (size_t)grow * F + tc * TN) =
                make_float4(acc[i][0], acc[i][1], acc[i][2], acc[i][3]);
    }
}

// ---------------- self-loop + bias init ----------------
// out[n,j] = sum_r b[r,j] + sum_r rsi_r[n]*rso_r[n]*xw_r[n,j]
template<int F>
__global__ void k_selfinit(const float* __restrict__ xw, const float* __restrict__ b,
                           float* __restrict__ out) {
    int i = blockIdx.x * blockDim.x + threadIdx.x;
    if (i >= N * F) return;
    int n = i / F, j = i % F;
    float v = b[0 * F + j] + b[1 * F + j] + b[2 * F + j];
#pragma unroll
    for (int r = 0; r < R; r++) {
        float w = g_rsi[r * N + n] * g_rso[r * N + n];
        v = fmaf(w, xw[((size_t)r * N + n) * F + j], v);
    }
    out[i] = v;
}

// ---------------- edge scatter ----------------
// out[d,:] += rso_r[s]*rsi_r[d] * xw_r[s,:]   via red.global.add.v4.f32
template<int F>
__global__ void k_scatter(const int* __restrict__ src, const int* __restrict__ dst,
                          const float* __restrict__ xw, float* __restrict__ out) {
    constexpr int V = F / 4;                 // float4s per row (32 or 16)
    int i = blockIdx.x * blockDim.x + threadIdx.x;
    if (i >= R * E * V) return;
    int q = i % V;
    int e = i / V;          // flat (r,e): src/dst are [R,E] flattened
    int r = e / E;
    int s = src[e], d = dst[e];
    float w = g_rso[r * N + s] * g_rsi[r * N + d];
    float4 v = *(const float4*)(xw + ((size_t)r * N + s) * F + q * 4);
    float* p = out + (size_t)d * F + q * 4;
    asm volatile("red.global.add.v4.f32 [%0], {%1,%2,%3,%4};"
                 :: "l"(p), "f"(v.x * w), "f"(v.y * w), "f"(v.z * w), "f"(v.w * w)
                 : "memory");
}

// ---------------- launch ----------------
extern "C" void kernel_launch(void* const* d_in, const int* in_sizes, int n_in,
                              void* d_out, int out_size) {
    const float* x   = (const float*)d_in[0];
    const int*   src = (const int*)d_in[1];
    const int*   dst = (const int*)d_in[2];
    const float* W1  = (const float*)d_in[3];
    const float* b1  = (const float*)d_in[4];
    const float* W2  = (const float*)d_in[5];
    const float* b2  = (const float*)d_in[6];
    float* out = (float*)d_out;

    float *xw1, *acc, *xw2;
    cudaGetSymbolAddress((void**)&xw1, g_xw1);
    cudaGetSymbolAddress((void**)&acc, g_acc);
    cudaGetSymbolAddress((void**)&xw2, g_xw2);

    // degrees (shared by both layers)
    k_deg_init<<<(R * N + 255) / 256, 256>>>();
    k_deg_count<<<(R * E + 255) / 256, 256>>>(src, dst);
    k_rsqrt<<<(R * N + 255) / 256, 256>>>();

    dim3 gg((N + 63) / 64, R);

    // layer 1: XW1_r = x @ W1_r ; ACC = selfloops+bias ; scatter edges
    gemm_rel<FHID, 8, false><<<gg, 256>>>(x, W1, xw1, N);
    k_selfinit<FHID><<<(N * FHID + 255) / 256, 256>>>(xw1, b1, acc);
    {
        int threads = R * E * (FHID / 4);
        k_scatter<FHID><<<(threads + 255) / 256, 256>>>(src, dst, xw1, acc);
    }

    // layer 2: XW2_r = relu(ACC) @ W2_r ; OUT = selfloops+bias ; scatter edges
    gemm_rel<FOUT, 4, true><<<gg, 256>>>(acc, W2, xw2, N);
    k_selfinit<FOUT><<<(N * FOUT + 255) / 256, 256>>>(xw2, b2, out);
    {
        int threads = R * E * (FOUT / 4);
        k_scatter<FOUT><<<(threads + 255) / 256, 256>>>(src, dst, xw2, out);
    }
}

// round 2
// speedup vs baseline: 1.6113x; 1.6113x over previous
#include <cuda_runtime.h>

// Problem constants (fixed by the dataset)
constexpr int N  = 50000;
constexpr int E  = 800000;
constexpr int R  = 3;
constexpr int FHID = 128;
constexpr int FOUT = 64;
constexpr int RN = R * N;
constexpr int RE = R * E;

constexpr int SCAN_BLK = 512;
constexpr int NSCAN = (RN + SCAN_BLK - 1) / SCAN_BLK;   // 293

// Scratch (device globals; no allocation allowed)
__device__ int   g_dego[RN];
__device__ int   g_degi[RN];
__device__ float g_rso[RN];
__device__ float g_rsi[RN];
__device__ int   g_off[RN + 1];
__device__ int   g_cur[RN];
__device__ int   g_part[RN];
__device__ int   g_bsum[SCAN_BLK];          // >= NSCAN
__device__ int   g_eidx[RE];                // CSR: src per (rel,dst)-bin
__device__ float g_xw1[(size_t)R * N * FHID];   // 76.8 MB
__device__ float g_acc[(size_t)N * FHID];       // 25.6 MB
__device__ float g_xw2[(size_t)R * N * FOUT];   // 38.4 MB

// ---------------- degrees ----------------
__global__ void k_deg_init() {
    int i = blockIdx.x * blockDim.x + threadIdx.x;
    if (i < RN) { g_dego[i] = 1; g_degi[i] = 1; }  // self-loop
}

__global__ void k_deg_count(const int* __restrict__ src, const int* __restrict__ dst) {
    int i = blockIdx.x * blockDim.x + threadIdx.x;
    if (i < RE) {
        int r = i / E;
        atomicAdd(&g_dego[r * N + src[i]], 1);
        atomicAdd(&g_degi[r * N + dst[i]], 1);
    }
}

__global__ void k_rsqrt() {
    int i = blockIdx.x * blockDim.x + threadIdx.x;
    if (i < RN) {
        g_rso[i] = rsqrtf((float)g_dego[i]);
        g_rsi[i] = rsqrtf((float)g_degi[i]);
    }
}

// ---------------- CSR build: exclusive scan of per-bin edge counts ----------------
__global__ __launch_bounds__(SCAN_BLK) void k_scan1() {
    __shared__ int s[SCAN_BLK];
    int t = threadIdx.x;
    int i = blockIdx.x * SCAN_BLK + t;
    int v = (i < RN) ? (g_degi[i] - 1) : 0;   // edge-only in-degree
    s[t] = v;
    __syncthreads();
#pragma unroll
    for (int off = 1; off < SCAN_BLK; off <<= 1) {
        int u = (t >= off) ? s[t - off] : 0;
        __syncthreads();
        s[t] += u;
        __syncthreads();
    }
    if (i < RN) g_part[i] = s[t];             // inclusive
    if (t == SCAN_BLK - 1) g_bsum[blockIdx.x] = s[t];
}

__global__ __launch_bounds__(SCAN_BLK) void k_scan2() {
    __shared__ int s[SCAN_BLK];
    int t = threadIdx.x;
    int v = (t < NSCAN) ? g_bsum[t] : 0;
    s[t] = v;
    __syncthreads();
#pragma unroll
    for (int off = 1; off < SCAN_BLK; off <<= 1) {
        int u = (t >= off) ? s[t - off] : 0;
        __syncthreads();
        s[t] += u;
        __syncthreads();
    }
    if (t < NSCAN) g_bsum[t] = s[t] - v;      // exclusive
}

__global__ void k_scan3() {
    int i = blockIdx.x * blockDim.x + threadIdx.x;
    if (i < RN) {
        int cnt = g_degi[i] - 1;
        int excl = g_part[i] - cnt + g_bsum[i / SCAN_BLK];
        g_off[i] = excl;
        g_cur[i] = excl;
    }
    if (i == 0) g_off[RN] = RE;
}

__global__ void k_fill(const int* __restrict__ src, const int* __restrict__ dst) {
    int i = blockIdx.x * blockDim.x + threadIdx.x;
    if (i < RE) {
        int r = i / E;
        int pos = atomicAdd(&g_cur[r * N + dst[i]], 1);
        g_eidx[pos] = src[i];
    }
}

// ---------------- GEMM: C_r = (relu?)(A) @ W_r  for r in grid.y ----------------
template<int F, int TM, bool RELU>
__global__ __launch_bounds__(256)
void gemm_rel(const float* __restrict__ A, const float* __restrict__ Wb,
              float* __restrict__ Cb, int nrows) {
    constexpr int K  = 128;
    constexpr int KT = 16;
    constexpr int TN = 4;
    constexpr int NTC = F / TN;
    constexpr int NTR = 256 / NTC;
    constexpr int BM  = NTR * TM;      // 64
    static_assert(BM == 64, "block row tile must be 64");

    const int r = blockIdx.y;
    const float* B = Wb + (size_t)r * K * F;
    float* C = Cb + (size_t)r * nrows * F;
    const int row0 = blockIdx.x * BM;
    const int tid = threadIdx.x;
    const int tc = tid % NTC;
    const int tr = tid / NTC;

    __shared__ float sA[KT][BM + 4];
    __shared__ float sB[KT][F];

    float acc[TM][TN];
#pragma unroll
    for (int i = 0; i < TM; i++)
#pragma unroll
        for (int j = 0; j < TN; j++) acc[i][j] = 0.f;

    for (int k0 = 0; k0 < K; k0 += KT) {
        {
            int m  = tid >> 2;
            int kq = tid & 3;
            int grow = row0 + m;
            float4 v = make_float4(0.f, 0.f, 0.f, 0.f);
            if (grow < nrows)
                v = *(const float4*)(A + (size_t)grow * K + k0 + kq * 4);
            if (RELU) {
                v.x = fmaxf(v.x, 0.f); v.y = fmaxf(v.y, 0.f);
                v.z = fmaxf(v.z, 0.f); v.w = fmaxf(v.w, 0.f);
            }
            sA[kq * 4 + 0][m] = v.x; sA[kq * 4 + 1][m] = v.y;
            sA[kq * 4 + 2][m] = v.z; sA[kq * 4 + 3][m] = v.w;
        }
        {
            constexpr int NF4 = KT * F / 4;
#pragma unroll
            for (int t = tid; t < NF4; t += 256) {
                int k  = t / (F / 4);
                int j4 = t % (F / 4);
                *(float4*)&sB[k][j4 * 4] = *(const float4*)(B + (size_t)(k0 + k) * F + j4 * 4);
            }
        }
        __syncthreads();
#pragma unroll
        for (int k = 0; k < KT; k++) {
            float a[TM], b[TN];
#pragma unroll
            for (int i = 0; i < TM; i += 4)
                *(float4*)&a[i] = *(const float4*)&sA[k][tr * TM + i];
            *(float4*)&b[0] = *(const float4*)&sB[k][tc * TN];
#pragma unroll
            for (int i = 0; i < TM; i++)
#pragma unroll
                for (int j = 0; j < TN; j++)
                    acc[i][j] = fmaf(a[i], b[j], acc[i][j]);
        }
        __syncthreads();
    }
#pragma unroll
    for (int i = 0; i < TM; i++) {
        int grow = row0 + tr * TM + i;
        if (grow < nrows)
            *(float4*)(C + (size_t)grow * F + tc * TN) =
                make_float4(acc[i][0], acc[i][1], acc[i][2], acc[i][3]);
    }
}

// ---------------- fused gather + selfloop + bias, F=128 ----------------
// out[d,:] = sum_r b_r + sum_r rsi_r[d] * ( rso_r[d]*xw_r[d,:] + sum_{e: dst=d} rso_r[s]*xw_r[s,:] )
__global__ __launch_bounds__(256)
void k_gather128(const float* __restrict__ xw, const float* __restrict__ b,
                 float* __restrict__ out) {
    int w = (blockIdx.x * blockDim.x + threadIdx.x) >> 5;
    int lane = threadIdx.x & 31;
    if (w >= N) return;
    int c = lane * 4;

    float4 b0 = *(const float4*)(b + 0 * FHID + c);
    float4 b1 = *(const float4*)(b + 1 * FHID + c);
    float4 b2 = *(const float4*)(b + 2 * FHID + c);
    float4 tot = make_float4(b0.x + b1.x + b2.x, b0.y + b1.y + b2.y,
                             b0.z + b1.z + b2.z, b0.w + b1.w + b2.w);

#pragma unroll
    for (int r = 0; r < R; r++) {
        const int bin = r * N + w;
        const float* base = xw + (size_t)r * N * FHID;
        float4 a = make_float4(0.f, 0.f, 0.f, 0.f);
        int j0 = g_off[bin], j1 = g_off[bin + 1];
#pragma unroll 4
        for (int j = j0; j < j1; j++) {
            int s = __ldg(&g_eidx[j]);
            float wt = g_rso[r * N + s];
            float4 v = *(const float4*)(base + (size_t)s * FHID + c);
            a.x = fmaf(wt, v.x, a.x); a.y = fmaf(wt, v.y, a.y);
            a.z = fmaf(wt, v.z, a.z); a.w = fmaf(wt, v.w, a.w);
        }
        float ws = g_rso[bin];
        float4 v = *(const float4*)(base + (size_t)w * FHID + c);
        a.x = fmaf(ws, v.x, a.x); a.y = fmaf(ws, v.y, a.y);
        a.z = fmaf(ws, v.z, a.z); a.w = fmaf(ws, v.w, a.w);
        float ri = g_rsi[bin];
        tot.x = fmaf(ri, a.x, tot.x); tot.y = fmaf(ri, a.y, tot.y);
        tot.z = fmaf(ri, a.z, tot.z); tot.w = fmaf(ri, a.w, tot.w);
    }
    *(float4*)(out + (size_t)w * FHID + c) = tot;
}

// ---------------- fused gather + selfloop + bias, F=64 ----------------
__global__ __launch_bounds__(256)
void k_gather64(const float* __restrict__ xw, const float* __restrict__ b,
                float* __restrict__ out) {
    int w = (blockIdx.x * blockDim.x + threadIdx.x) >> 5;
    int lane = threadIdx.x & 31;
    if (w >= N) return;
    int c = lane * 2;

    float2 b0 = *(const float2*)(b + 0 * FOUT + c);
    float2 b1 = *(const float2*)(b + 1 * FOUT + c);
    float2 b2 = *(const float2*)(b + 2 * FOUT + c);
    float2 tot = make_float2(b0.x + b1.x + b2.x, b0.y + b1.y + b2.y);

#pragma unroll
    for (int r = 0; r < R; r++) {
        const int bin = r * N + w;
        const float* base = xw + (size_t)r * N * FOUT;
        float2 a = make_float2(0.f, 0.f);
        int j0 = g_off[bin], j1 = g_off[bin + 1];
#pragma unroll 4
        for (int j = j0; j < j1; j++) {
            int s = __ldg(&g_eidx[j]);
            float wt = g_rso[r * N + s];
            float2 v = *(const float2*)(base + (size_t)s * FOUT + c);
            a.x = fmaf(wt, v.x, a.x); a.y = fmaf(wt, v.y, a.y);
        }
        float ws = g_rso[bin];
        float2 v = *(const float2*)(base + (size_t)w * FOUT + c);
        a.x = fmaf(ws, v.x, a.x); a.y = fmaf(ws, v.y, a.y);
        float ri = g_rsi[bin];
        tot.x = fmaf(ri, a.x, tot.x); tot.y = fmaf(ri, a.y, tot.y);
    }
    *(float2*)(out + (size_t)w * FOUT + c) = tot;
}

// ---------------- launch ----------------
extern "C" void kernel_launch(void* const* d_in, const int* in_sizes, int n_in,
                              void* d_out, int out_size) {
    const float* x   = (const float*)d_in[0];
    const int*   src = (const int*)d_in[1];
    const int*   dst = (const int*)d_in[2];
    const float* W1  = (const float*)d_in[3];
    const float* b1  = (const float*)d_in[4];
    const float* W2  = (const float*)d_in[5];
    const float* b2  = (const float*)d_in[6];
    float* out = (float*)d_out;

    float *xw1, *acc, *xw2;
    cudaGetSymbolAddress((void**)&xw1, g_xw1);
    cudaGetSymbolAddress((void**)&acc, g_acc);
    cudaGetSymbolAddress((void**)&xw2, g_xw2);

    // degrees + CSR (shared by both layers)
    k_deg_init<<<(RN + 255) / 256, 256>>>();
    k_deg_count<<<(RE + 255) / 256, 256>>>(src, dst);
    k_rsqrt<<<(RN + 255) / 256, 256>>>();
    k_scan1<<<NSCAN, SCAN_BLK>>>();
    k_scan2<<<1, SCAN_BLK>>>();
    k_scan3<<<(RN + 255) / 256, 256>>>();
    k_fill<<<(RE + 255) / 256, 256>>>(src, dst);

    dim3 gg((N + 63) / 64, R);
    const int gwarps = (N * 32 + 255) / 256;

    // layer 1
    gemm_rel<FHID, 8, false><<<gg, 256>>>(x, W1, xw1, N);
    k_gather128<<<gwarps, 256>>>(xw1, b1, acc);

    // layer 2
    gemm_rel<FOUT, 4, true><<<gg, 256>>>(acc, W2, xw2, N);
    k_gather64<<<gwarps, 256>>>(xw2, b2, out);
}